// round 1
// baseline (speedup 1.0000x reference)
#include <cuda_runtime.h>

// BoxRenderLoss: for each of B box pairs, sample 100 fragments inside each box,
// mask by "outside the other box", weight by min squared distance to 100 sampled
// boundary points of the other box; average over everything.
//
// Boundary points = 4 edges x 25 linspace samples -> separable per-axis min:
//   min over {X0,X1}x{y_k}  = min((px-X0)^2,(px-X1)^2) + min_k (py-y_k)^2
//   min over {x_k}x{Y0,Y1}  = min((py-Y0)^2,(py-Y1)^2) + min_k (px-x_k)^2
// nearest evenly-spaced sample found analytically (round + clamp, check +-1).

#define THREADS 256
#define MAX_BLOCKS 8192

__device__ float g_partial[MAX_BLOCKS];

// min over k=0..24 of (p - (k*(1/24)*len + lo))^2, matching reference sampling
__device__ __forceinline__ float edge_min_sq(float p, float lo, float len) {
    const float DB = 1.0f / 24.0f;
    float tc = (p - lo) * 24.0f / len;           // continuous nearest index
    // NaN-safe clamp: fminf/fmaxf return the non-NaN operand
    float k0f = fminf(fmaxf(roundf(tc), 0.0f), 24.0f);
    int k0 = (int)k0f;
    float best = 3.4e38f;
#pragma unroll
    for (int dk = -1; dk <= 1; ++dk) {
        int k = min(max(k0 + dk, 0), 24);
        float s = fmaf((float)k * DB, len, lo);  // same formula as reference
        float dd = p - s;
        best = fminf(best, dd * dd);
    }
    return best;
}

__global__ __launch_bounds__(THREADS)
void box_render_loss_kernel(const float4* __restrict__ boxes,
                            const float4* __restrict__ targets,
                            int ntasks) {
    int t = blockIdx.x * THREADS + threadIdx.x;
    float val = 0.0f;
    if (t < ntasks) {
        int f  = t % 100;          // fragment index
        int bd = t / 100;
        int d  = bd & 1;           // direction: 0 = box frags vs target, 1 = swap
        int b  = bd >> 1;          // pair index

        float4 A = boxes[b];
        float4 T = targets[b];
        float4 F = d ? T : A;      // fragment-source box
        float4 O = d ? A : T;      // other box

        const float DF = 1.0f / 9.0f;
        float fw = F.z - F.x, fh = F.w - F.y;
        float px = fmaf((float)(f / 10) * DF, fw, F.x);
        float py = fmaf((float)(f % 10) * DF, fh, F.y);

        // outside mask (inclusive inside test, as in reference)
        bool inside = (px - O.x >= 0.0f) && (py - O.y >= 0.0f) &&
                      (O.z - px >= 0.0f) && (O.w - py >= 0.0f);
        if (!inside) {
            float ow = O.z - O.x, oh = O.w - O.y;
            float X1 = ow + O.x;   // 1*ow + O.x, exactly as reference computes it
            float Y1 = oh + O.y;

            float dymin = edge_min_sq(py, O.y, oh);
            float dx0 = px - O.x, dx1 = px - X1;
            float dvert = fminf(dx0 * dx0, dx1 * dx1) + dymin;

            float dxmin = edge_min_sq(px, O.x, ow);
            float dy0 = py - O.y, dy1 = py - Y1;
            float dhorz = fminf(dy0 * dy0, dy1 * dy1) + dxmin;

            val = fminf(dvert, dhorz);
        }
    }

    // block reduction: warp shuffles, then across warps via shared
    unsigned mask = 0xffffffffu;
#pragma unroll
    for (int o = 16; o > 0; o >>= 1)
        val += __shfl_down_sync(mask, val, o);

    __shared__ float ws[THREADS / 32];
    int lane = threadIdx.x & 31;
    int wid  = threadIdx.x >> 5;
    if (lane == 0) ws[wid] = val;
    __syncthreads();
    if (wid == 0) {
        float v = (lane < THREADS / 32) ? ws[lane] : 0.0f;
#pragma unroll
        for (int o = (THREADS / 32) / 2; o > 0; o >>= 1)
            v += __shfl_down_sync(mask, v, o);
        if (lane == 0) g_partial[blockIdx.x] = v;
    }
}

__global__ __launch_bounds__(1024)
void final_reduce_kernel(int n, float* __restrict__ out, double scale) {
    __shared__ double sd[1024];
    double s = 0.0;
    for (int i = threadIdx.x; i < n; i += 1024)
        s += (double)g_partial[i];
    sd[threadIdx.x] = s;
    __syncthreads();
#pragma unroll
    for (int o = 512; o > 0; o >>= 1) {
        if (threadIdx.x < o) sd[threadIdx.x] += sd[threadIdx.x + o];
        __syncthreads();
    }
    if (threadIdx.x == 0)
        out[0] = (float)(sd[0] * scale);
}

extern "C" void kernel_launch(void* const* d_in, const int* in_sizes, int n_in,
                              void* d_out, int out_size) {
    const float4* boxes   = (const float4*)d_in[0];
    const float4* targets = (const float4*)d_in[1];
    float* out = (float*)d_out;

    int B = in_sizes[0] / 4;          // 4096
    int ntasks = B * 200;             // 2 directions * 100 fragments
    int nblocks = (ntasks + THREADS - 1) / THREADS;  // 3200
    if (nblocks > MAX_BLOCKS) nblocks = MAX_BLOCKS;  // safety (not expected)

    double scale = 1.0 / (2.0 * (double)B * 100.0);

    box_render_loss_kernel<<<nblocks, THREADS>>>(boxes, targets, ntasks);
    final_reduce_kernel<<<1, 1024>>>(nblocks, out, scale);
}

// round 2
// speedup vs baseline: 2.6277x; 2.6277x over previous
#include <cuda_runtime.h>

// BoxRenderLoss, single fused launch.
//
// Boundary points = 4 edges x 25 linspace samples -> separable per-axis min:
//   min over {X0,X1}x{y_k}  = min((px-X0)^2,(px-X1)^2) + min_k (py-y_k)^2
//   min over {x_k}x{Y0,Y1}  = min((py-Y0)^2,(py-Y1)^2) + min_k (px-x_k)^2
// Nearest evenly-spaced sample found analytically (round + clamp, probe +-1).
//
// Thread layout: one thread per (pair b, direction d, fragment-row r).
// px / x-edge terms hoisted out of the 10-iteration py loop.
//
// Reduction: block reduce -> one double atomicAdd per block into a device
// scratch accumulator; last block (fenced ticket) writes the scaled scalar
// and resets the scratch so the launch is graph-replayable.

#define THREADS 256

__device__ double g_sum = 0.0;          // zero-init; last block restores 0
__device__ unsigned int g_ticket = 0;   // atomicInc with wrap auto-resets

// min over k=0..24 of (p - (k*(1/24)*len + lo))^2, matching reference sampling
__device__ __forceinline__ float edge_min_sq(float p, float lo, float len) {
    const float DB = 1.0f / 24.0f;
    float tc = (p - lo) * 24.0f / len;             // continuous nearest index
    // NaN-safe clamp (len==0 -> tc NaN -> k0=0; all samples coincide anyway)
    float k0f = fminf(fmaxf(roundf(tc), 0.0f), 24.0f);
    int k0 = (int)k0f;
    float best = 3.4e38f;
#pragma unroll
    for (int dk = -1; dk <= 1; ++dk) {
        int k = min(max(k0 + dk, 0), 24);
        float s = fmaf((float)k * DB, len, lo);    // same formula as reference
        float dd = p - s;
        best = fminf(best, dd * dd);
    }
    return best;
}

__global__ __launch_bounds__(THREADS)
void box_render_loss_fused(const float4* __restrict__ boxes,
                           const float4* __restrict__ targets,
                           float* __restrict__ out,
                           int ntasks, double scale, unsigned int nblocks) {
    int t = blockIdx.x * THREADS + threadIdx.x;
    float val = 0.0f;
    if (t < ntasks) {
        int row = t % 10;          // fragment row -> px
        int d   = (t / 10) & 1;    // direction: 0 = box frags vs target, 1 = swap
        int b   = t / 20;          // pair index

        float4 A = boxes[b];
        float4 T = targets[b];
        float4 F = d ? T : A;      // fragment-source box
        float4 O = d ? A : T;      // other box

        const float DF = 1.0f / 9.0f;
        float fw = F.z - F.x, fh = F.w - F.y;
        float px = fmaf((float)row * DF, fw, F.x);

        float ow = O.z - O.x, oh = O.w - O.y;
        float X1 = ow + O.x;       // 1*ow + O.x, exactly as reference computes it
        float Y1 = oh + O.y;

        // x-dependent terms, hoisted across the 10 py values
        bool in_x   = (px - O.x >= 0.0f) && (O.z - px >= 0.0f);
        float dx0 = px - O.x, dx1 = px - X1;
        float vert_x = fminf(dx0 * dx0, dx1 * dx1);      // to vertical edges, x part
        float dxmin  = edge_min_sq(px, O.x, ow);         // to horizontal edges, x part

#pragma unroll
        for (int fi = 0; fi < 10; ++fi) {
            float py = fmaf((float)fi * DF, fh, F.y);
            bool inside = in_x && (py - O.y >= 0.0f) && (O.w - py >= 0.0f);
            if (!inside) {
                float dymin = edge_min_sq(py, O.y, oh);
                float dy0 = py - O.y, dy1 = py - Y1;
                float horz = fminf(dy0 * dy0, dy1 * dy1) + dxmin;
                val += fminf(vert_x + dymin, horz);
            }
        }
    }

    // block reduction: warp shuffles, then across warps via shared
    unsigned mask = 0xffffffffu;
#pragma unroll
    for (int o = 16; o > 0; o >>= 1)
        val += __shfl_down_sync(mask, val, o);

    __shared__ float ws[THREADS / 32];
    int lane = threadIdx.x & 31;
    int wid  = threadIdx.x >> 5;
    if (lane == 0) ws[wid] = val;
    __syncthreads();

    if (wid == 0) {
        float v = (lane < THREADS / 32) ? ws[lane] : 0.0f;
#pragma unroll
        for (int o = (THREADS / 32) / 2; o > 0; o >>= 1)
            v += __shfl_down_sync(mask, v, o);

        if (lane == 0) {
            atomicAdd(&g_sum, (double)v);
            __threadfence();
            // wraps back to 0 when it reaches nblocks-1 -> self-resetting
            unsigned int ticket = atomicInc(&g_ticket, nblocks - 1u);
            if (ticket == nblocks - 1u) {
                double s = g_sum;          // all adds visible (atomics + fences)
                out[0] = (float)(s * scale);
                g_sum = 0.0;               // restore for next graph replay
                __threadfence();
            }
        }
    }
}

extern "C" void kernel_launch(void* const* d_in, const int* in_sizes, int n_in,
                              void* d_out, int out_size) {
    const float4* boxes   = (const float4*)d_in[0];
    const float4* targets = (const float4*)d_in[1];
    float* out = (float*)d_out;

    int B = in_sizes[0] / 4;                 // 4096
    int ntasks = B * 20;                     // 2 directions * 10 rows
    unsigned int nblocks = (unsigned int)((ntasks + THREADS - 1) / THREADS); // 320

    double scale = 1.0 / (2.0 * (double)B * 100.0);

    box_render_loss_fused<<<nblocks, THREADS>>>(boxes, targets, out,
                                                ntasks, scale, nblocks);
}